// round 15
// baseline (speedup 1.0000x reference)
#include <cuda_runtime.h>
#include <cuda_fp16.h>
#include <cstdint>
#include <math.h>

#define N_NODES 100000
#define N_EDGES 1000000
#define SCAN_BLK 98               // ceil(100000 / 1024)
#define OFF_MASK 0x03FFFFFFu      // col*256 lives in bits [8,25); row&15 in bits [26,30)

// ---------------- scratch (static device globals; no allocation) ----------------
__device__ __half g_H[(size_t)N_NODES * 128];   // [N][128] fp16 : x@W0 | x@W1
__device__ __half g_T[(size_t)N_NODES * 64];    // [N][64]  fp16 : A h1
__device__ float  g_deg1[N_NODES];              // A 1

// CSR build scratch (g_cnt zero at load; re-zeroed by scan1 each call)
__device__ int   g_cnt[N_NODES];
__device__ int   g_cur[N_NODES];                // scatter cursors (init = row ptr)
__device__ int   g_ptr[N_NODES + 1];            // row_ptr (exclusive)
__device__ int   g_blk[128];                    // block sums for scan
__device__ unsigned long long g_edge[N_EDGES];  // {val:32 | rloc:4 | col*256:26}

// ---------------- histogram of rows ----------------
__global__ void hist_kernel(const int* __restrict__ ei) {
    const int stride = gridDim.x * blockDim.x;
    const int4* R4 = (const int4*)ei;
    for (int i = blockIdx.x * blockDim.x + threadIdx.x; i < N_EDGES / 4; i += stride) {
        int4 r = __ldg(&R4[i]);
        atomicAdd(&g_cnt[r.x], 1);
        atomicAdd(&g_cnt[r.y], 1);
        atomicAdd(&g_cnt[r.z], 1);
        atomicAdd(&g_cnt[r.w], 1);
    }
}

// ---------------- scan stage 1: per-block exclusive scan; also re-zero g_cnt --------
__global__ __launch_bounds__(256) void scan1_kernel() {
    __shared__ int sh[256];
    const int t = threadIdx.x;
    const int base = blockIdx.x * 1024 + t * 4;
    int c0 = (base + 0 < N_NODES) ? g_cnt[base + 0] : 0;
    int c1 = (base + 1 < N_NODES) ? g_cnt[base + 1] : 0;
    int c2 = (base + 2 < N_NODES) ? g_cnt[base + 2] : 0;
    int c3 = (base + 3 < N_NODES) ? g_cnt[base + 3] : 0;
    if (base + 0 < N_NODES) g_cnt[base + 0] = 0;
    if (base + 1 < N_NODES) g_cnt[base + 1] = 0;
    if (base + 2 < N_NODES) g_cnt[base + 2] = 0;
    if (base + 3 < N_NODES) g_cnt[base + 3] = 0;
    int tsum = c0 + c1 + c2 + c3;
    sh[t] = tsum;
    __syncthreads();
    for (int off = 1; off < 256; off <<= 1) {
        int v = (t >= off) ? sh[t - off] : 0;
        __syncthreads();
        if (t >= off) sh[t] += v;
        __syncthreads();
    }
    int excl = (t > 0) ? sh[t - 1] : 0;
    if (t == 255) g_blk[blockIdx.x] = sh[255];
    if (base + 0 < N_NODES) g_ptr[base + 0] = excl;
    if (base + 1 < N_NODES) g_ptr[base + 1] = excl + c0;
    if (base + 2 < N_NODES) g_ptr[base + 2] = excl + c0 + c1;
    if (base + 3 < N_NODES) g_ptr[base + 3] = excl + c0 + c1 + c2;
}

// ---- scan stage 2+3 fused ----
__global__ __launch_bounds__(256) void scan3_kernel() {
    __shared__ int off[128];
    const int t = threadIdx.x;
    if (t < 32) {
        const int base = t * 4;
        int c0 = (base + 0 < SCAN_BLK) ? g_blk[base + 0] : 0;
        int c1 = (base + 1 < SCAN_BLK) ? g_blk[base + 1] : 0;
        int c2 = (base + 2 < SCAN_BLK) ? g_blk[base + 2] : 0;
        int c3 = (base + 3 < SCAN_BLK) ? g_blk[base + 3] : 0;
        int tsum = c0 + c1 + c2 + c3;
        int incl = tsum;
#pragma unroll
        for (int o = 1; o < 32; o <<= 1) {
            int u = __shfl_up_sync(0xffffffffu, incl, o);
            if (t >= o) incl += u;
        }
        int excl = incl - tsum;
        off[base + 0] = excl;
        off[base + 1] = excl + c0;
        off[base + 2] = excl + c0 + c1;
        off[base + 3] = excl + c0 + c1 + c2;
    }
    __syncthreads();
    const int stride = gridDim.x * blockDim.x;
    for (int i = blockIdx.x * blockDim.x + t; i < N_NODES; i += stride) {
        int p = g_ptr[i] + off[i >> 10];
        g_ptr[i] = p;
        g_cur[i] = p;
    }
    if (blockIdx.x == 0 && t == 0) g_ptr[N_NODES] = N_EDGES;
}

// ---------------- scatter edges into CSR order (4 edges/thread, packed) -----------
// packs: val (hi 32) | (row&15)<<26 | col*256
__global__ void scatter_kernel(const int* __restrict__ ei, const float* __restrict__ ea) {
    const int q = blockIdx.x * blockDim.x + threadIdx.x;
    if (q >= N_EDGES / 4) return;
    int4 r = __ldg(&((const int4*)ei)[q]);
    int4 c = __ldg(&((const int4*)(ei + N_EDGES))[q]);
    float4 v = __ldg(&((const float4*)ea)[q]);
    int p0 = atomicAdd(&g_cur[r.x], 1);
    int p1 = atomicAdd(&g_cur[r.y], 1);
    int p2 = atomicAdd(&g_cur[r.z], 1);
    int p3 = atomicAdd(&g_cur[r.w], 1);
    g_edge[p0] = ((unsigned long long)__float_as_uint(v.x) << 32) |
                 (((unsigned int)r.x & 15u) << 26) | ((unsigned int)c.x << 8);
    g_edge[p1] = ((unsigned long long)__float_as_uint(v.y) << 32) |
                 (((unsigned int)r.y & 15u) << 26) | ((unsigned int)c.y << 8);
    g_edge[p2] = ((unsigned long long)__float_as_uint(v.z) << 32) |
                 (((unsigned int)r.z & 15u) << 26) | ((unsigned int)c.z << 8);
    g_edge[p3] = ((unsigned long long)__float_as_uint(v.w) << 32) |
                 (((unsigned int)r.w & 15u) << 26) | ((unsigned int)c.w << 8);
}

// ---------------- tensor-core GEMM: H = fp16( x @ [W0|W1] ) ----------------
#define SM_STRIDE 136

__device__ __forceinline__ unsigned int smem_u32(const void* p) {
    unsigned int a;
    asm("{ .reg .u64 t; cvta.to.shared.u64 t, %1; cvt.u32.u64 %0, t; }"
        : "=r"(a) : "l"(p));
    return a;
}

__global__ __launch_bounds__(256) void gemm_kernel(const float* __restrict__ x,
                                                   const float* __restrict__ W0,
                                                   const float* __restrict__ W1) {
    extern __shared__ __half smem_dyn[];
    __half* As = smem_dyn;                         // [128][SM_STRIDE]
    __half* Bs = smem_dyn + 128 * SM_STRIDE;       // [128][SM_STRIDE]

    const int tid = threadIdx.x;
    const int r0 = blockIdx.x * 128;

    const float4* W04 = (const float4*)W0;
    const float4* W14 = (const float4*)W1;
    for (int i = tid; i < 2048; i += 256) {
        int k = i >> 4, c4 = i & 15;
        float4 v0 = __ldg(&W04[i]);
        float4 v1 = __ldg(&W14[i]);
        __half2 a01 = __floats2half2_rn(v0.x, v0.y);
        __half2 a23 = __floats2half2_rn(v0.z, v0.w);
        __half2 b01 = __floats2half2_rn(v1.x, v1.y);
        __half2 b23 = __floats2half2_rn(v1.z, v1.w);
        *(uint2*)&Bs[k * SM_STRIDE + c4 * 4] =
            make_uint2(*(unsigned int*)&a01, *(unsigned int*)&a23);
        *(uint2*)&Bs[k * SM_STRIDE + 64 + c4 * 4] =
            make_uint2(*(unsigned int*)&b01, *(unsigned int*)&b23);
    }
    const float4* x4 = (const float4*)x;
    for (int i = tid; i < 4096; i += 256) {
        int r = i >> 5, c4 = i & 31;
        float4 v = (r0 + r < N_NODES) ? __ldg(&x4[(size_t)(r0 + r) * 32 + c4])
                                      : make_float4(0.f, 0.f, 0.f, 0.f);
        __half2 h01 = __floats2half2_rn(v.x, v.y);
        __half2 h23 = __floats2half2_rn(v.z, v.w);
        *(uint2*)&As[r * SM_STRIDE + c4 * 4] =
            make_uint2(*(unsigned int*)&h01, *(unsigned int*)&h23);
    }
    __syncthreads();

    const int w = tid >> 5;
    const int lane = tid & 31;
    const unsigned int As_u = smem_u32(As);
    const unsigned int Bs_u = smem_u32(Bs);

    const int arow = w * 16 + (lane & 7) + (lane & 8);
    const int acol8 = (lane >> 4) & 1;
    const int bls = lane & 15;

    float acc[16][4];
#pragma unroll
    for (int n = 0; n < 16; n++)
#pragma unroll
        for (int c = 0; c < 4; c++) acc[n][c] = 0.f;

#pragma unroll
    for (int kk = 0; kk < 8; kk++) {
        unsigned int a0, a1, a2, a3;
        unsigned int addrA = As_u + (unsigned int)((arow * SM_STRIDE + kk * 16 + acol8 * 8) * 2);
        asm volatile("ldmatrix.sync.aligned.m8n8.x4.shared.b16 {%0,%1,%2,%3}, [%4];"
                     : "=r"(a0), "=r"(a1), "=r"(a2), "=r"(a3) : "r"(addrA));
        unsigned int addrB0 = Bs_u + (unsigned int)(((kk * 16 + bls) * SM_STRIDE) * 2);
#pragma unroll
        for (int n = 0; n < 16; n++) {
            unsigned int bm0, bm1;
            unsigned int addrB = addrB0 + (unsigned int)(n * 16);
            asm volatile("ldmatrix.sync.aligned.m8n8.x2.trans.shared.b16 {%0,%1}, [%2];"
                         : "=r"(bm0), "=r"(bm1) : "r"(addrB));
            asm volatile(
                "mma.sync.aligned.m16n8k16.row.col.f32.f16.f16.f32 "
                "{%0,%1,%2,%3}, {%4,%5,%6,%7}, {%8,%9}, {%0,%1,%2,%3};"
                : "+f"(acc[n][0]), "+f"(acc[n][1]), "+f"(acc[n][2]), "+f"(acc[n][3])
                : "r"(a0), "r"(a1), "r"(a2), "r"(a3), "r"(bm0), "r"(bm1));
        }
    }

    const int rA = r0 + w * 16 + (lane >> 2);
    const int colb = (lane & 3) * 2;
#pragma unroll
    for (int n = 0; n < 16; n++) {
        int col = n * 8 + colb;
        if (rA < N_NODES) {
            __half2 h = __floats2half2_rn(acc[n][0], acc[n][1]);
            *(__half2*)&g_H[(size_t)rA * 128 + col] = h;
        }
        if (rA + 8 < N_NODES) {
            __half2 h = __floats2half2_rn(acc[n][2], acc[n][3]);
            *(__half2*)&g_H[(size_t)(rA + 8) * 128 + col] = h;
        }
    }
}

// ---------------- host-side stream/event objects (created once at load) ----------
namespace {
struct ForkCtx {
    cudaStream_t s2;
    cudaEvent_t evF, evG;
    ForkCtx() {
        cudaStreamCreateWithFlags(&s2, cudaStreamNonBlocking);
        cudaEventCreateWithFlags(&evF, cudaEventDisableTiming);
        cudaEventCreateWithFlags(&evG, cudaEventDisableTiming);
        cudaFuncSetAttribute(gemm_kernel, cudaFuncAttributeMaxDynamicSharedMemorySize,
                             2 * 128 * SM_STRIDE * (int)sizeof(__half));
    }
};
ForkCtx g_fork;
}

// ================= spmm1 via tensor cores =========================================
// Block = 128 threads (4 warps), handles 16 rows. D[16,128+deg] = sum A[16,16]*B[16,129]
// A[i,k] = v_k if chunk-edge k belongs to local row i, else 0 (fp16).
// B[k,:] = H[col_k] (fp16), col 128 = 1.0 (degree column).
#define HS_STRIDE 136              // halves; same conflict-free stride as gemm
#define AS_STRIDE 24               // halves; 48B row stride -> conflict-free ldmatrix
#define DS_STRIDE 132              // floats

__global__ __launch_bounds__(128) void spmm1_kernel(const float* __restrict__ b0,
                                                    const float* __restrict__ fc0,
                                                    const float* __restrict__ bf0,
                                                    float* __restrict__ out) {
    __shared__ __half As[16 * AS_STRIDE];
    __shared__ __half Hs[16 * HS_STRIDE];
    __shared__ int    colbuf[16];
    __shared__ float  Ds[16 * DS_STRIDE];

    const int tid = threadIdx.x;
    const int warp = tid >> 5;
    const int lane = tid & 31;
    const int r0 = blockIdx.x * 16;
    const int base = g_ptr[r0];
    const int end = g_ptr[r0 + 16];

    // ones column for degree
    if (tid < 16) Hs[tid * HS_STRIDE + 128] = __float2half(1.f);

    const unsigned int As_u = smem_u32(As);
    const unsigned int Hs_u = smem_u32(Hs);
    // A frag address (row-major, non-trans x4): same pattern as gemm_kernel
    const unsigned int addrA =
        As_u + (unsigned int)((((lane & 7) + (lane & 8)) * AS_STRIDE + ((lane >> 4) & 1) * 8) * 2);
    // B frag address base (k-major, trans x2): row = k = lane&15
    const unsigned int addrB_row = Hs_u + (unsigned int)(((lane & 15) * HS_STRIDE) * 2);

    float acc[4][4];
#pragma unroll
    for (int n = 0; n < 4; n++)
#pragma unroll
        for (int c = 0; c < 4; c++) acc[n][c] = 0.f;
    float dacc[4] = {0.f, 0.f, 0.f, 0.f};         // degree tile (warp 0 only)

    for (int chunk = base; chunk < end; chunk += 16) {
        __syncthreads();                           // previous mma done with As/Hs
        if (tid < 16) {
            // zero my A row (cols 0..15 = 32B)
            *(uint4*)&As[tid * AS_STRIDE + 0] = make_uint4(0, 0, 0, 0);
            *(uint4*)&As[tid * AS_STRIDE + 8] = make_uint4(0, 0, 0, 0);
            int j = chunk + tid;
            unsigned long long p = (j < end) ? g_edge[j] : 0ull;
            unsigned int lo = (unsigned int)p;
            unsigned int off = lo & OFF_MASK;
            int rloc = (lo >> 26) & 15;
            float v = __uint_as_float((unsigned int)(p >> 32));
            if (j >= end) { v = 0.f; off = 0; rloc = 0; }
            colbuf[tid] = (int)off;
            __syncwarp(0x0000ffffu);               // rows zeroed before column writes
            As[rloc * AS_STRIDE + tid] = __float2half(v);
        }
        __syncthreads();                           // colbuf + As ready
        // cooperative gather: 16 rows x 256B into Hs
        {
            int k = tid >> 3;
            int seg = tid & 7;
            const char* src = (const char*)g_H + colbuf[k];
            uint4 d0 = *(const uint4*)(src + seg * 16);
            uint4 d1 = *(const uint4*)(src + (seg + 8) * 16);
            *(uint4*)&Hs[k * HS_STRIDE + seg * 8] = d0;
            *(uint4*)&Hs[k * HS_STRIDE + (seg + 8) * 8] = d1;
        }
        __syncthreads();
        // MMA: warp w covers cols [w*32, w*32+32)
        unsigned int a0, a1, a2, a3;
        asm volatile("ldmatrix.sync.aligned.m8n8.x4.shared.b16 {%0,%1,%2,%3}, [%4];"
                     : "=r"(a0), "=r"(a1), "=r"(a2), "=r"(a3) : "r"(addrA));
#pragma unroll
        for (int n = 0; n < 4; n++) {
            unsigned int bm0, bm1;
            unsigned int ab = addrB_row + (unsigned int)((warp * 32 + n * 8) * 2);
            asm volatile("ldmatrix.sync.aligned.m8n8.x2.trans.shared.b16 {%0,%1}, [%2];"
                         : "=r"(bm0), "=r"(bm1) : "r"(ab));
            asm volatile(
                "mma.sync.aligned.m16n8k16.row.col.f32.f16.f16.f32 "
                "{%0,%1,%2,%3}, {%4,%5,%6,%7}, {%8,%9}, {%0,%1,%2,%3};"
                : "+f"(acc[n][0]), "+f"(acc[n][1]), "+f"(acc[n][2]), "+f"(acc[n][3])
                : "r"(a0), "r"(a1), "r"(a2), "r"(a3), "r"(bm0), "r"(bm1));
        }
        if (warp == 0) {                           // degree tile (cols 128..135)
            unsigned int bm0, bm1;
            unsigned int ab = addrB_row + (unsigned int)(128 * 2);
            asm volatile("ldmatrix.sync.aligned.m8n8.x2.trans.shared.b16 {%0,%1}, [%2];"
                         : "=r"(bm0), "=r"(bm1) : "r"(ab));
            asm volatile(
                "mma.sync.aligned.m16n8k16.row.col.f32.f16.f16.f32 "
                "{%0,%1,%2,%3}, {%4,%5,%6,%7}, {%8,%9}, {%0,%1,%2,%3};"
                : "+f"(dacc[0]), "+f"(dacc[1]), "+f"(dacc[2]), "+f"(dacc[3])
                : "r"(a0), "r"(a1), "r"(a2), "r"(a3), "r"(bm0), "r"(bm1));
        }
    }
    __syncthreads();                               // Hs/As free; now fill Ds

    // write D fragments to smem: lane holds rows (lane>>2, +8), cols (lane&3)*2
    {
        int row = lane >> 2;
        int colb = (lane & 3) * 2;
#pragma unroll
        for (int n = 0; n < 4; n++) {
            int col = warp * 32 + n * 8 + colb;
            Ds[row * DS_STRIDE + col] = acc[n][0];
            Ds[row * DS_STRIDE + col + 1] = acc[n][1];
            Ds[(row + 8) * DS_STRIDE + col] = acc[n][2];
            Ds[(row + 8) * DS_STRIDE + col + 1] = acc[n][3];
        }
        if (warp == 0 && colb == 0) {
            Ds[row * DS_STRIDE + 128] = dacc[0];
            Ds[(row + 8) * DS_STRIDE + 128] = dacc[2];
        }
    }
    __syncthreads();

    // epilogue: warp w handles rows 4w..4w+3 (existing proven math)
    for (int r = 0; r < 4; r++) {
        const int row = warp * 4 + r;
        const int node = r0 + row;
        float4 acc4 = *(float4*)&Ds[row * DS_STRIDE + lane * 4];
        float deg = Ds[row * DS_STRIDE + 128];

        const int l4 = (lane & 15) * 4;
        float inv = (deg > 0.f) ? (1.f / deg) : 0.f;
        float4 y;
        y.x = acc4.x * inv + __ldg(&b0[l4 + 0]);
        y.y = acc4.y * inv + __ldg(&b0[l4 + 1]);
        y.z = acc4.z * inv + __ldg(&b0[l4 + 2]);
        y.w = acc4.w * inv + __ldg(&b0[l4 + 3]);
        float dot = y.x * __ldg(&fc0[l4 + 0]) + y.y * __ldg(&fc0[l4 + 1]) +
                    y.z * __ldg(&fc0[l4 + 2]) + y.w * __ldg(&fc0[l4 + 3]);
#pragma unroll
        for (int o = 8; o; o >>= 1) dot += __shfl_xor_sync(0xffffffffu, dot, o);
        float g = 1.f / (1.f + expf(-(dot + __ldg(&bf0[0]))));

        if (lane < 16) {
            float4 o;
            o.x = (y.x > 0.f) ? y.x : g * y.x;
            o.y = (y.y > 0.f) ? y.y : g * y.y;
            o.z = (y.z > 0.f) ? y.z : g * y.z;
            o.w = (y.w > 0.f) ? y.w : g * y.w;
            *(float4*)&out[(size_t)node * 128 + l4] = o;
        } else {
            __half2 t0 = __floats2half2_rn(acc4.x, acc4.y);
            __half2 t1 = __floats2half2_rn(acc4.z, acc4.w);
            *(uint2*)&g_T[(size_t)node * 64 + l4] =
                make_uint2(*(unsigned int*)&t0, *(unsigned int*)&t1);
        }
        if (lane == 0) g_deg1[node] = deg;
    }
}

// ---- pass 2 + hop1 epilogue: warp per row, 4-edge unroll, fp16 T gathers ----------
__device__ __forceinline__ void unpack_edge2(unsigned long long p, unsigned int& off,
                                             float& v) {
    off = (unsigned int)p & OFF_MASK;              // col*256
    v = __uint_as_float((unsigned int)(p >> 32));
}

__global__ __launch_bounds__(256) void spmm2_kernel(const float* __restrict__ b1,
                                                    const float* __restrict__ fc1,
                                                    const float* __restrict__ bf1,
                                                    float* __restrict__ out) {
    const int w = (blockIdx.x * 256 + threadIdx.x) >> 5;
    const int lane = threadIdx.x & 31;
    if (w >= N_NODES) return;
    const int s = g_ptr[w];
    const int e = g_ptr[w + 1];
    const char* Tb = (const char*)g_T + lane * 4;

    float2 acc = make_float2(0.f, 0.f);
    float deg = 0.f;
    int i = s;
    for (; i + 4 <= e; i += 4) {
        unsigned int o0, o1, o2, o3;
        float v0, v1, v2, v3;
        unpack_edge2(g_edge[i + 0], o0, v0);
        unpack_edge2(g_edge[i + 1], o1, v1);
        unpack_edge2(g_edge[i + 2], o2, v2);
        unpack_edge2(g_edge[i + 3], o3, v3);
        unsigned int u0 = *(const unsigned int*)(Tb + (o0 >> 1));
        unsigned int u1 = *(const unsigned int*)(Tb + (o1 >> 1));
        unsigned int u2 = *(const unsigned int*)(Tb + (o2 >> 1));
        unsigned int u3 = *(const unsigned int*)(Tb + (o3 >> 1));
        float d0 = __ldg(&g_deg1[o0 >> 8]);
        float d1 = __ldg(&g_deg1[o1 >> 8]);
        float d2 = __ldg(&g_deg1[o2 >> 8]);
        float d3 = __ldg(&g_deg1[o3 >> 8]);
        float2 t0 = __half22float2(*(__half2*)&u0);
        float2 t1 = __half22float2(*(__half2*)&u1);
        float2 t2 = __half22float2(*(__half2*)&u2);
        float2 t3 = __half22float2(*(__half2*)&u3);
        acc.x += v0 * t0.x + v1 * t1.x + v2 * t2.x + v3 * t3.x;
        acc.y += v0 * t0.y + v1 * t1.y + v2 * t2.y + v3 * t3.y;
        deg += (v0 * d0 + v1 * d1) + (v2 * d2 + v3 * d3);
    }
    for (; i < e; i++) {
        unsigned int o0;
        float v0;
        unpack_edge2(g_edge[i], o0, v0);
        unsigned int u0 = *(const unsigned int*)(Tb + (o0 >> 1));
        float2 t0 = __half22float2(*(__half2*)&u0);
        acc.x += v0 * t0.x;
        acc.y += v0 * t0.y;
        deg += v0 * __ldg(&g_deg1[o0 >> 8]);
    }

    float inv = (deg > 0.f) ? (1.f / deg) : 0.f;
    float2 y;
    y.x = acc.x * inv + __ldg(&b1[2 * lane]);
    y.y = acc.y * inv + __ldg(&b1[2 * lane + 1]);
    float dot = y.x * __ldg(&fc1[2 * lane]) + y.y * __ldg(&fc1[2 * lane + 1]);
#pragma unroll
    for (int o = 16; o; o >>= 1) dot += __shfl_xor_sync(0xffffffffu, dot, o);
    float g = 1.f / (1.f + expf(-(dot + __ldg(&bf1[0]))));

    float2 o;
    o.x = (y.x > 0.f) ? y.x : g * y.x;
    o.y = (y.y > 0.f) ? y.y : g * y.y;
    *(float2*)&out[(size_t)w * 128 + 64 + 2 * lane] = o;
}

// ---------------- launch ----------------
extern "C" void kernel_launch(void* const* d_in, const int* in_sizes, int n_in,
                              void* d_out, int out_size) {
    const float* x   = (const float*)d_in[0];
    const int*   ei  = (const int*)d_in[1];
    const float* ea  = (const float*)d_in[2];
    const float* W0  = (const float*)d_in[3];
    const float* b0  = (const float*)d_in[4];
    const float* W1  = (const float*)d_in[5];
    const float* b1  = (const float*)d_in[6];
    const float* fc0 = (const float*)d_in[7];
    const float* bf0 = (const float*)d_in[8];
    const float* fc1 = (const float*)d_in[9];
    const float* bf1 = (const float*)d_in[10];
    float* out = (float*)d_out;

    // Fork: GEMM on side stream, CSR build on main stream.
    cudaEventRecord(g_fork.evF, 0);
    cudaStreamWaitEvent(g_fork.s2, g_fork.evF, 0);

    const int gemm_smem = 2 * 128 * SM_STRIDE * (int)sizeof(__half);
    gemm_kernel<<<(N_NODES + 127) / 128, 256, gemm_smem, g_fork.s2>>>(x, W0, W1);
    cudaEventRecord(g_fork.evG, g_fork.s2);

    hist_kernel<<<512, 256>>>(ei);
    scan1_kernel<<<SCAN_BLK, 256>>>();
    scan3_kernel<<<392, 256>>>();
    scatter_kernel<<<(N_EDGES / 4 + 255) / 256, 256>>>(ei, ea);

    // Join: spmm1 needs both the CSR (main stream) and g_H (side stream).
    cudaStreamWaitEvent(0, g_fork.evG, 0);

    spmm1_kernel<<<N_NODES / 16, 128>>>(b0, fc0, bf0, out);
    spmm2_kernel<<<(N_NODES * 32 + 255) / 256, 256>>>(b1, fc1, bf1, out);
}

// round 16
// speedup vs baseline: 1.1640x; 1.1640x over previous
#include <cuda_runtime.h>
#include <cuda_fp16.h>
#include <cstdint>
#include <math.h>

#define N_NODES 100000
#define N_EDGES 1000000
#define SCAN_BLK 98               // ceil(100000 / 1024)

// ---------------- scratch (static device globals; no allocation) ----------------
__device__ __half g_H[(size_t)N_NODES * 128];   // [N][128] fp16 : x@W0 | x@W1
__device__ __half g_T[(size_t)N_NODES * 64];    // [N][64]  fp16 : A h1
__device__ float  g_deg1[N_NODES];              // A 1

// CSR build scratch (g_cnt zero at load; re-zeroed by scan1 each call)
__device__ int   g_cnt[N_NODES];
__device__ int   g_eidx[N_EDGES];               // within-row index (from hist)
__device__ int   g_ptr[N_NODES + 1];            // row_ptr (exclusive)
__device__ int   g_blk[128];                    // block sums for scan
__device__ unsigned long long g_edge[N_EDGES];  // packed {val_bits:32 | col*256:32}

// ---------------- histogram of rows; also record within-row index ----------------
__global__ void hist_kernel(const int* __restrict__ ei) {
    const int stride = gridDim.x * blockDim.x;
    const int4* R4 = (const int4*)ei;
    int4* E4 = (int4*)g_eidx;
    for (int i = blockIdx.x * blockDim.x + threadIdx.x; i < N_EDGES / 4; i += stride) {
        int4 r = __ldg(&R4[i]);
        int4 idx;
        idx.x = atomicAdd(&g_cnt[r.x], 1);
        idx.y = atomicAdd(&g_cnt[r.y], 1);
        idx.z = atomicAdd(&g_cnt[r.z], 1);
        idx.w = atomicAdd(&g_cnt[r.w], 1);
        E4[i] = idx;
    }
}

// ---------------- scan stage 1: per-block exclusive scan; also re-zero g_cnt --------
__global__ __launch_bounds__(256) void scan1_kernel() {
    __shared__ int sh[256];
    const int t = threadIdx.x;
    const int base = blockIdx.x * 1024 + t * 4;
    int c0 = (base + 0 < N_NODES) ? g_cnt[base + 0] : 0;
    int c1 = (base + 1 < N_NODES) ? g_cnt[base + 1] : 0;
    int c2 = (base + 2 < N_NODES) ? g_cnt[base + 2] : 0;
    int c3 = (base + 3 < N_NODES) ? g_cnt[base + 3] : 0;
    if (base + 0 < N_NODES) g_cnt[base + 0] = 0;
    if (base + 1 < N_NODES) g_cnt[base + 1] = 0;
    if (base + 2 < N_NODES) g_cnt[base + 2] = 0;
    if (base + 3 < N_NODES) g_cnt[base + 3] = 0;
    int tsum = c0 + c1 + c2 + c3;
    sh[t] = tsum;
    __syncthreads();
    for (int off = 1; off < 256; off <<= 1) {
        int v = (t >= off) ? sh[t - off] : 0;
        __syncthreads();
        if (t >= off) sh[t] += v;
        __syncthreads();
    }
    int excl = (t > 0) ? sh[t - 1] : 0;
    if (t == 255) g_blk[blockIdx.x] = sh[255];
    if (base + 0 < N_NODES) g_ptr[base + 0] = excl;
    if (base + 1 < N_NODES) g_ptr[base + 1] = excl + c0;
    if (base + 2 < N_NODES) g_ptr[base + 2] = excl + c0 + c1;
    if (base + 3 < N_NODES) g_ptr[base + 3] = excl + c0 + c1 + c2;
}

// ---- scan stage 2+3 fused: redundant warp-scan of block sums + add offsets ----
__global__ __launch_bounds__(256) void scan3_kernel() {
    __shared__ int off[128];
    const int t = threadIdx.x;
    if (t < 32) {
        const int base = t * 4;
        int c0 = (base + 0 < SCAN_BLK) ? g_blk[base + 0] : 0;
        int c1 = (base + 1 < SCAN_BLK) ? g_blk[base + 1] : 0;
        int c2 = (base + 2 < SCAN_BLK) ? g_blk[base + 2] : 0;
        int c3 = (base + 3 < SCAN_BLK) ? g_blk[base + 3] : 0;
        int tsum = c0 + c1 + c2 + c3;
        int incl = tsum;
#pragma unroll
        for (int o = 1; o < 32; o <<= 1) {
            int u = __shfl_up_sync(0xffffffffu, incl, o);
            if (t >= o) incl += u;
        }
        int excl = incl - tsum;
        off[base + 0] = excl;
        off[base + 1] = excl + c0;
        off[base + 2] = excl + c0 + c1;
        off[base + 3] = excl + c0 + c1 + c2;
    }
    __syncthreads();
    const int stride = gridDim.x * blockDim.x;
    for (int i = blockIdx.x * blockDim.x + t; i < N_NODES; i += stride)
        g_ptr[i] += off[i >> 10];
    if (blockIdx.x == 0 && t == 0) g_ptr[N_NODES] = N_EDGES;
}

// ---------------- scatter edges into CSR order (NO atomics) ----------------------
// pos = g_ptr[row] + g_eidx[e]; stores col premultiplied by 256.
__global__ void scatter_kernel(const int* __restrict__ ei, const float* __restrict__ ea) {
    const int q = blockIdx.x * blockDim.x + threadIdx.x;
    if (q >= N_EDGES / 4) return;
    int4 r = __ldg(&((const int4*)ei)[q]);
    int4 c = __ldg(&((const int4*)(ei + N_EDGES))[q]);
    float4 v = __ldg(&((const float4*)ea)[q]);
    int4 idx = ((const int4*)g_eidx)[q];
    int p0 = g_ptr[r.x] + idx.x;
    int p1 = g_ptr[r.y] + idx.y;
    int p2 = g_ptr[r.z] + idx.z;
    int p3 = g_ptr[r.w] + idx.w;
    g_edge[p0] = ((unsigned long long)__float_as_uint(v.x) << 32) | ((unsigned int)c.x << 8);
    g_edge[p1] = ((unsigned long long)__float_as_uint(v.y) << 32) | ((unsigned int)c.y << 8);
    g_edge[p2] = ((unsigned long long)__float_as_uint(v.z) << 32) | ((unsigned int)c.z << 8);
    g_edge[p3] = ((unsigned long long)__float_as_uint(v.w) << 32) | ((unsigned int)c.w << 8);
}

// ---------------- tensor-core GEMM: H = fp16( x @ [W0|W1] ) ----------------
#define SM_STRIDE 136

__device__ __forceinline__ unsigned int smem_u32(const void* p) {
    unsigned int a;
    asm("{ .reg .u64 t; cvta.to.shared.u64 t, %1; cvt.u32.u64 %0, t; }"
        : "=r"(a) : "l"(p));
    return a;
}

__global__ __launch_bounds__(256) void gemm_kernel(const float* __restrict__ x,
                                                   const float* __restrict__ W0,
                                                   const float* __restrict__ W1) {
    extern __shared__ __half smem_dyn[];
    __half* As = smem_dyn;                         // [128][SM_STRIDE]
    __half* Bs = smem_dyn + 128 * SM_STRIDE;       // [128][SM_STRIDE]

    const int tid = threadIdx.x;
    const int r0 = blockIdx.x * 128;

    const float4* W04 = (const float4*)W0;
    const float4* W14 = (const float4*)W1;
    for (int i = tid; i < 2048; i += 256) {
        int k = i >> 4, c4 = i & 15;
        float4 v0 = __ldg(&W04[i]);
        float4 v1 = __ldg(&W14[i]);
        __half2 a01 = __floats2half2_rn(v0.x, v0.y);
        __half2 a23 = __floats2half2_rn(v0.z, v0.w);
        __half2 b01 = __floats2half2_rn(v1.x, v1.y);
        __half2 b23 = __floats2half2_rn(v1.z, v1.w);
        *(uint2*)&Bs[k * SM_STRIDE + c4 * 4] =
            make_uint2(*(unsigned int*)&a01, *(unsigned int*)&a23);
        *(uint2*)&Bs[k * SM_STRIDE + 64 + c4 * 4] =
            make_uint2(*(unsigned int*)&b01, *(unsigned int*)&b23);
    }
    const float4* x4 = (const float4*)x;
    for (int i = tid; i < 4096; i += 256) {
        int r = i >> 5, c4 = i & 31;
        float4 v = (r0 + r < N_NODES) ? __ldg(&x4[(size_t)(r0 + r) * 32 + c4])
                                      : make_float4(0.f, 0.f, 0.f, 0.f);
        __half2 h01 = __floats2half2_rn(v.x, v.y);
        __half2 h23 = __floats2half2_rn(v.z, v.w);
        *(uint2*)&As[r * SM_STRIDE + c4 * 4] =
            make_uint2(*(unsigned int*)&h01, *(unsigned int*)&h23);
    }
    __syncthreads();

    const int w = tid >> 5;
    const int lane = tid & 31;
    const unsigned int As_u = smem_u32(As);
    const unsigned int Bs_u = smem_u32(Bs);

    const int arow = w * 16 + (lane & 7) + (lane & 8);
    const int acol8 = (lane >> 4) & 1;
    const int bls = lane & 15;

    float acc[16][4];
#pragma unroll
    for (int n = 0; n < 16; n++)
#pragma unroll
        for (int c = 0; c < 4; c++) acc[n][c] = 0.f;

#pragma unroll
    for (int kk = 0; kk < 8; kk++) {
        unsigned int a0, a1, a2, a3;
        unsigned int addrA = As_u + (unsigned int)((arow * SM_STRIDE + kk * 16 + acol8 * 8) * 2);
        asm volatile("ldmatrix.sync.aligned.m8n8.x4.shared.b16 {%0,%1,%2,%3}, [%4];"
                     : "=r"(a0), "=r"(a1), "=r"(a2), "=r"(a3) : "r"(addrA));
        unsigned int addrB0 = Bs_u + (unsigned int)(((kk * 16 + bls) * SM_STRIDE) * 2);
#pragma unroll
        for (int n = 0; n < 16; n++) {
            unsigned int bm0, bm1;
            unsigned int addrB = addrB0 + (unsigned int)(n * 16);
            asm volatile("ldmatrix.sync.aligned.m8n8.x2.trans.shared.b16 {%0,%1}, [%2];"
                         : "=r"(bm0), "=r"(bm1) : "r"(addrB));
            asm volatile(
                "mma.sync.aligned.m16n8k16.row.col.f32.f16.f16.f32 "
                "{%0,%1,%2,%3}, {%4,%5,%6,%7}, {%8,%9}, {%0,%1,%2,%3};"
                : "+f"(acc[n][0]), "+f"(acc[n][1]), "+f"(acc[n][2]), "+f"(acc[n][3])
                : "r"(a0), "r"(a1), "r"(a2), "r"(a3), "r"(bm0), "r"(bm1));
        }
    }

    const int rA = r0 + w * 16 + (lane >> 2);
    const int colb = (lane & 3) * 2;
#pragma unroll
    for (int n = 0; n < 16; n++) {
        int col = n * 8 + colb;
        if (rA < N_NODES) {
            __half2 h = __floats2half2_rn(acc[n][0], acc[n][1]);
            *(__half2*)&g_H[(size_t)rA * 128 + col] = h;
        }
        if (rA + 8 < N_NODES) {
            __half2 h = __floats2half2_rn(acc[n][2], acc[n][3]);
            *(__half2*)&g_H[(size_t)(rA + 8) * 128 + col] = h;
        }
    }
}

// ---------------- host-side stream/event objects (created once at load) ----------
namespace {
struct ForkCtx {
    cudaStream_t s2;
    cudaEvent_t evF, evG;
    ForkCtx() {
        cudaStreamCreateWithFlags(&s2, cudaStreamNonBlocking);
        cudaEventCreateWithFlags(&evF, cudaEventDisableTiming);
        cudaEventCreateWithFlags(&evG, cudaEventDisableTiming);
        cudaFuncSetAttribute(gemm_kernel, cudaFuncAttributeMaxDynamicSharedMemorySize,
                             2 * 128 * SM_STRIDE * (int)sizeof(__half));
    }
};
ForkCtx g_fork;
}

// ---------------- SpMM helpers ----------------
__device__ __forceinline__ void unpack_edge(unsigned long long p, unsigned int& off,
                                            float& v) {
    off = (unsigned int)p;                         // col*256 (byte offset in g_H)
    v = __uint_as_float((unsigned int)(p >> 32));
}
__device__ __forceinline__ unsigned long long pack2(float a, float b) {
    unsigned long long r;
    asm("mov.b64 %0, {%1, %2};" : "=l"(r) : "f"(a), "f"(b));
    return r;
}
__device__ __forceinline__ void ffma2(unsigned long long& d, unsigned long long a,
                                      unsigned long long b) {
    asm("fma.rn.f32x2 %0, %1, %2, %0;" : "+l"(d) : "l"(a), "l"(b));
}
__device__ __forceinline__ float2 unpack2(unsigned long long v) {
    float2 f;
    asm("mov.b64 {%0, %1}, %2;" : "=f"(f.x), "=f"(f.y) : "l"(v));
    return f;
}
__device__ __forceinline__ void ld_half4_p(const char* p, unsigned long long& lo,
                                           unsigned long long& hi) {
    uint2 u = *(const uint2*)p;
    float2 a = __half22float2(*(__half2*)&u.x);
    float2 b = __half22float2(*(__half2*)&u.y);
    lo = pack2(a.x, a.y);
    hi = pack2(b.x, b.y);
}

// ---- pass 1 + hop0 epilogue: warp per row, 4-edge unroll, fp16 gathers -----------
__global__ __launch_bounds__(256) void spmm1_kernel(const float* __restrict__ b0,
                                                    const float* __restrict__ fc0,
                                                    const float* __restrict__ bf0,
                                                    float* __restrict__ out) {
    const int w = (blockIdx.x * 256 + threadIdx.x) >> 5;
    const int lane = threadIdx.x & 31;
    if (w >= N_NODES) return;
    const int s = g_ptr[w];
    const int e = g_ptr[w + 1];
    const char* Hb = (const char*)g_H + lane * 8;

    unsigned long long acc01 = 0ull, acc23 = 0ull;
    float deg = 0.f;
    int i = s;
    for (; i + 4 <= e; i += 4) {
        unsigned int o0, o1, o2, o3;
        float v0, v1, v2, v3;
        unpack_edge(g_edge[i + 0], o0, v0);
        unpack_edge(g_edge[i + 1], o1, v1);
        unpack_edge(g_edge[i + 2], o2, v2);
        unpack_edge(g_edge[i + 3], o3, v3);
        unsigned long long h0l, h0h, h1l, h1h, h2l, h2h, h3l, h3h;
        ld_half4_p(Hb + o0, h0l, h0h);
        ld_half4_p(Hb + o1, h1l, h1h);
        ld_half4_p(Hb + o2, h2l, h2h);
        ld_half4_p(Hb + o3, h3l, h3h);
        unsigned long long vv0 = pack2(v0, v0);
        unsigned long long vv1 = pack2(v1, v1);
        unsigned long long vv2 = pack2(v2, v2);
        unsigned long long vv3 = pack2(v3, v3);
        ffma2(acc01, h0l, vv0); ffma2(acc23, h0h, vv0);
        ffma2(acc01, h1l, vv1); ffma2(acc23, h1h, vv1);
        ffma2(acc01, h2l, vv2); ffma2(acc23, h2h, vv2);
        ffma2(acc01, h3l, vv3); ffma2(acc23, h3h, vv3);
        deg += (v0 + v1) + (v2 + v3);
    }
    for (; i < e; i++) {
        unsigned int o0;
        float v0;
        unpack_edge(g_edge[i], o0, v0);
        unsigned long long h0l, h0h;
        ld_half4_p(Hb + o0, h0l, h0h);
        unsigned long long vv0 = pack2(v0, v0);
        ffma2(acc01, h0l, vv0);
        ffma2(acc23, h0h, vv0);
        deg += v0;
    }

    float2 a01 = unpack2(acc01);
    float2 a23 = unpack2(acc23);
    float4 acc = make_float4(a01.x, a01.y, a23.x, a23.y);

    const int l4 = (lane & 15) * 4;
    float inv = (deg > 0.f) ? (1.f / deg) : 0.f;
    float4 y;
    y.x = acc.x * inv + __ldg(&b0[l4 + 0]);
    y.y = acc.y * inv + __ldg(&b0[l4 + 1]);
    y.z = acc.z * inv + __ldg(&b0[l4 + 2]);
    y.w = acc.w * inv + __ldg(&b0[l4 + 3]);
    float dot = y.x * __ldg(&fc0[l4 + 0]) + y.y * __ldg(&fc0[l4 + 1]) +
                y.z * __ldg(&fc0[l4 + 2]) + y.w * __ldg(&fc0[l4 + 3]);
#pragma unroll
    for (int o = 8; o; o >>= 1) dot += __shfl_xor_sync(0xffffffffu, dot, o);
    float g = 1.f / (1.f + expf(-(dot + __ldg(&bf0[0]))));

    if (lane < 16) {
        float4 o;
        o.x = (y.x > 0.f) ? y.x : g * y.x;
        o.y = (y.y > 0.f) ? y.y : g * y.y;
        o.z = (y.z > 0.f) ? y.z : g * y.z;
        o.w = (y.w > 0.f) ? y.w : g * y.w;
        *(float4*)&out[(size_t)w * 128 + l4] = o;
    } else {
        __half2 t0 = __floats2half2_rn(acc.x, acc.y);
        __half2 t1 = __floats2half2_rn(acc.z, acc.w);
        *(uint2*)&g_T[(size_t)w * 64 + l4] =
            make_uint2(*(unsigned int*)&t0, *(unsigned int*)&t1);
    }
    if (lane == 0) g_deg1[w] = deg;
}

// ---- pass 2 + hop1 epilogue: warp per row, 4-edge unroll, fp16 T gathers ----------
__global__ __launch_bounds__(256) void spmm2_kernel(const float* __restrict__ b1,
                                                    const float* __restrict__ fc1,
                                                    const float* __restrict__ bf1,
                                                    float* __restrict__ out) {
    const int w = (blockIdx.x * 256 + threadIdx.x) >> 5;
    const int lane = threadIdx.x & 31;
    if (w >= N_NODES) return;
    const int s = g_ptr[w];
    const int e = g_ptr[w + 1];
    const char* Tb = (const char*)g_T + lane * 4;

    float2 acc = make_float2(0.f, 0.f);
    float deg = 0.f;
    int i = s;
    for (; i + 4 <= e; i += 4) {
        unsigned int o0, o1, o2, o3;
        float v0, v1, v2, v3;
        unpack_edge(g_edge[i + 0], o0, v0);
        unpack_edge(g_edge[i + 1], o1, v1);
        unpack_edge(g_edge[i + 2], o2, v2);
        unpack_edge(g_edge[i + 3], o3, v3);
        unsigned int u0 = *(const unsigned int*)(Tb + (o0 >> 1));
        unsigned int u1 = *(const unsigned int*)(Tb + (o1 >> 1));
        unsigned int u2 = *(const unsigned int*)(Tb + (o2 >> 1));
        unsigned int u3 = *(const unsigned int*)(Tb + (o3 >> 1));
        float d0 = __ldg(&g_deg1[o0 >> 8]);
        float d1 = __ldg(&g_deg1[o1 >> 8]);
        float d2 = __ldg(&g_deg1[o2 >> 8]);
        float d3 = __ldg(&g_deg1[o3 >> 8]);
        float2 t0 = __half22float2(*(__half2*)&u0);
        float2 t1 = __half22float2(*(__half2*)&u1);
        float2 t2 = __half22float2(*(__half2*)&u2);
        float2 t3 = __half22float2(*(__half2*)&u3);
        acc.x += v0 * t0.x + v1 * t1.x + v2 * t2.x + v3 * t3.x;
        acc.y += v0 * t0.y + v1 * t1.y + v2 * t2.y + v3 * t3.y;
        deg += (v0 * d0 + v1 * d1) + (v2 * d2 + v3 * d3);
    }
    for (; i < e; i++) {
        unsigned int o0;
        float v0;
        unpack_edge(g_edge[i], o0, v0);
        unsigned int u0 = *(const unsigned int*)(Tb + (o0 >> 1));
        float2 t0 = __half22float2(*(__half2*)&u0);
        acc.x += v0 * t0.x;
        acc.y += v0 * t0.y;
        deg += v0 * __ldg(&g_deg1[o0 >> 8]);
    }

    float inv = (deg > 0.f) ? (1.f / deg) : 0.f;
    float2 y;
    y.x = acc.x * inv + __ldg(&b1[2 * lane]);
    y.y = acc.y * inv + __ldg(&b1[2 * lane + 1]);
    float dot = y.x * __ldg(&fc1[2 * lane]) + y.y * __ldg(&fc1[2 * lane + 1]);
#pragma unroll
    for (int o = 16; o; o >>= 1) dot += __shfl_xor_sync(0xffffffffu, dot, o);
    float g = 1.f / (1.f + expf(-(dot + __ldg(&bf1[0]))));

    float2 o;
    o.x = (y.x > 0.f) ? y.x : g * y.x;
    o.y = (y.y > 0.f) ? y.y : g * y.y;
    *(float2*)&out[(size_t)w * 128 + 64 + 2 * lane] = o;
}

// ---------------- launch ----------------
extern "C" void kernel_launch(void* const* d_in, const int* in_sizes, int n_in,
                              void* d_out, int out_size) {
    const float* x   = (const float*)d_in[0];
    const int*   ei  = (const int*)d_in[1];
    const float* ea  = (const float*)d_in[2];
    const float* W0  = (const float*)d_in[3];
    const float* b0  = (const float*)d_in[4];
    const float* W1  = (const float*)d_in[5];
    const float* b1  = (const float*)d_in[6];
    const float* fc0 = (const float*)d_in[7];
    const float* bf0 = (const float*)d_in[8];
    const float* fc1 = (const float*)d_in[9];
    const float* bf1 = (const float*)d_in[10];
    float* out = (float*)d_out;

    // Fork: GEMM on side stream, CSR build on main stream (independent chains).
    cudaEventRecord(g_fork.evF, 0);
    cudaStreamWaitEvent(g_fork.s2, g_fork.evF, 0);

    const int gemm_smem = 2 * 128 * SM_STRIDE * (int)sizeof(__half);
    gemm_kernel<<<(N_NODES + 127) / 128, 256, gemm_smem, g_fork.s2>>>(x, W0, W1);
    cudaEventRecord(g_fork.evG, g_fork.s2);

    hist_kernel<<<512, 256>>>(ei);
    scan1_kernel<<<SCAN_BLK, 256>>>();
    scan3_kernel<<<392, 256>>>();
    scatter_kernel<<<(N_EDGES / 4 + 255) / 256, 256>>>(ei, ea);

    // Join: spmm1 needs both the CSR (main stream) and g_H (side stream).
    cudaStreamWaitEvent(0, g_fork.evG, 0);

    spmm1_kernel<<<(N_NODES * 32 + 255) / 256, 256>>>(b0, fc0, bf0, out);
    spmm2_kernel<<<(N_NODES * 32 + 255) / 256, 256>>>(b1, fc1, bf1, out);
}